// round 1
// baseline (speedup 1.0000x reference)
#include <cuda_runtime.h>
#include <cuda_bf16.h>

#define B   512
#define DIM 128
#define MARGIN 0.2f
#define EPSF   1e-6f

// Scratch (no allocation allowed in kernel_launch)
__device__ float g_D[B * B];
__device__ double g_num;
__device__ unsigned long long g_den;

// ---------------------------------------------------------------------------
// Kernel 0: zero accumulators (must run every call; graph-replayed)
// ---------------------------------------------------------------------------
__global__ void zero_acc_kernel() {
    g_num = 0.0;
    g_den = 0ull;
}

// ---------------------------------------------------------------------------
// Kernel 1: pairwise distances.
// 32x32 output tile per block, 256 threads as 16x16, each computes a 2x2
// micro-tile. Smem stride 129 (odd) -> conflict-free column reads.
// D[i,j] = sqrt( sum_d ((f_i[d] - f_j[d]) + eps)^2 )   (matches torch/ref order)
// ---------------------------------------------------------------------------
#define TS 32
#define LD 129
__global__ __launch_bounds__(256) void dist_kernel(const float* __restrict__ F) {
    __shared__ float Fi[TS * LD];
    __shared__ float Fj[TS * LD];

    const int tx = threadIdx.x & 15;
    const int ty = threadIdx.x >> 4;
    const int i0 = blockIdx.y * TS;
    const int j0 = blockIdx.x * TS;

    // Coalesced global load, conflict-free smem store (consecutive d per warp)
    for (int idx = threadIdx.x; idx < TS * DIM; idx += 256) {
        const int r = idx >> 7;       // row within tile
        const int d = idx & 127;      // feature dim
        Fi[r * LD + d] = F[(i0 + r) * DIM + d];
        Fj[r * LD + d] = F[(j0 + r) * DIM + d];
    }
    __syncthreads();

    const int ia = 2 * ty;
    const int ja = 2 * tx;
    float a00 = 0.f, a01 = 0.f, a10 = 0.f, a11 = 0.f;

#pragma unroll 8
    for (int d = 0; d < DIM; d++) {
        const float fi0 = Fi[ia * LD + d];
        const float fi1 = Fi[(ia + 1) * LD + d];
        const float fj0 = Fj[ja * LD + d];
        const float fj1 = Fj[(ja + 1) * LD + d];
        float x;
        x = (fi0 - fj0) + EPSF; a00 = fmaf(x, x, a00);
        x = (fi0 - fj1) + EPSF; a01 = fmaf(x, x, a01);
        x = (fi1 - fj0) + EPSF; a10 = fmaf(x, x, a10);
        x = (fi1 - fj1) + EPSF; a11 = fmaf(x, x, a11);
    }

    const int i = i0 + ia;
    const int j = j0 + ja;
    g_D[i * B + j]             = sqrtf(a00);
    g_D[i * B + j + 1]         = sqrtf(a01);
    g_D[(i + 1) * B + j]       = sqrtf(a10);
    g_D[(i + 1) * B + j + 1]   = sqrtf(a11);
}

// ---------------------------------------------------------------------------
// Kernel 2: triplet reduction. One block (256 threads) per anchor row.
// Builds positive / negative distance lists in smem, then for each positive
// sums relu(pos + margin - neg) over all negatives. Each thread owns at most
// two negatives (nn <= 511), hoisted into registers.
// ---------------------------------------------------------------------------
__global__ __launch_bounds__(256) void triplet_kernel(const int* __restrict__ mask) {
    __shared__ float s_pos[B];
    __shared__ float s_neg[B];
    __shared__ int   s_cnt[2];
    __shared__ float s_wsum[8];

    const int i   = blockIdx.x;
    const int tid = threadIdx.x;

    if (tid < 2) s_cnt[tid] = 0;
    __syncthreads();

    // Partition row i into positive / negative distance lists.
    for (int j = tid; j < B; j += 256) {
        const float d = g_D[i * B + j];
        const int   m = mask[i * B + j];
        if (m != 0) {
            const int p = atomicAdd(&s_cnt[0], 1);
            s_pos[p] = d;
        } else if (j != i) {
            const int p = atomicAdd(&s_cnt[1], 1);
            s_neg[p] = d;
        }
    }
    __syncthreads();

    const int np = s_cnt[0];
    const int nn = s_cnt[1];

    // Each thread owns negatives at tid and tid+256 (nn < 512).
    const float nk0 = (tid       < nn) ? s_neg[tid]       : 1e30f;
    const float nk1 = (tid + 256 < nn) ? s_neg[tid + 256] : 1e30f;

    float local = 0.f;
    for (int j = 0; j < np; j++) {
        const float pj = s_pos[j] + MARGIN;   // broadcast LDS
        local += fmaxf(pj - nk0, 0.f);
        local += fmaxf(pj - nk1, 0.f);
    }

    // Block reduce (warp shuffle -> smem -> thread 0)
#pragma unroll
    for (int off = 16; off; off >>= 1)
        local += __shfl_down_sync(0xffffffffu, local, off);
    if ((tid & 31) == 0) s_wsum[tid >> 5] = local;
    __syncthreads();
    if (tid == 0) {
        float s = 0.f;
#pragma unroll
        for (int w = 0; w < 8; w++) s += s_wsum[w];
        atomicAdd(&g_num, (double)s);
        atomicAdd(&g_den, (unsigned long long)np * (unsigned long long)nn);
    }
}

// ---------------------------------------------------------------------------
// Kernel 3: finalize scalar output
// ---------------------------------------------------------------------------
__global__ void finalize_kernel(float* __restrict__ out) {
    const double den = (double)g_den;
    out[0] = (den > 0.0) ? (float)(g_num / den) : 0.0f;
}

// ---------------------------------------------------------------------------
extern "C" void kernel_launch(void* const* d_in, const int* in_sizes, int n_in,
                              void* d_out, int out_size) {
    const float* features = (const float*)d_in[0];   // [512,128] f32
    const int*   mask     = (const int*)d_in[1];     // [512,512] i32
    float* out = (float*)d_out;

    zero_acc_kernel<<<1, 1>>>();

    dim3 grid1(B / TS, B / TS);  // 16 x 16 = 256 blocks
    dist_kernel<<<grid1, 256>>>(features);

    triplet_kernel<<<B, 256>>>(mask);

    finalize_kernel<<<1, 1>>>(out);
}

// round 2
// speedup vs baseline: 1.0928x; 1.0928x over previous
#include <cuda_runtime.h>
#include <cuda_bf16.h>

#define B      512
#define DIM    128
#define MARGIN 0.2f
#define EPSF   1e-6f

// Scratch state (allocation-free rule). Statics init to zero; the triplet
// kernel's last block resets them after use, so every call leaves them zero.
__device__ float g_D[B * B];
__device__ double g_num = 0.0;
__device__ unsigned long long g_den = 0ull;
__device__ unsigned int g_done = 0u;

// ---------------------------------------------------------------------------
// Kernel 1: pairwise distances.
// 32x32 output tile, 256 threads as 16x16, 2x2 register micro-tile.
// eps is folded into the Fi tile at load time: (fi + eps) - fj == fi - fj + eps
// which matches torch pairwise_distance / the reference exactly.
// ---------------------------------------------------------------------------
#define TS 32
#define LD 129
__global__ __launch_bounds__(256) void dist_kernel(const float* __restrict__ F) {
    __shared__ float Fi[TS * LD];   // holds fi + eps
    __shared__ float Fj[TS * LD];

    const int tx = threadIdx.x & 15;
    const int ty = threadIdx.x >> 4;
    const int i0 = blockIdx.y * TS;
    const int j0 = blockIdx.x * TS;

    for (int idx = threadIdx.x; idx < TS * DIM; idx += 256) {
        const int r = idx >> 7;
        const int d = idx & 127;
        Fi[r * LD + d] = F[(i0 + r) * DIM + d] + EPSF;
        Fj[r * LD + d] = F[(j0 + r) * DIM + d];
    }
    __syncthreads();

    const int ia = 2 * ty;
    const int ja = 2 * tx;
    float a00 = 0.f, a01 = 0.f, a10 = 0.f, a11 = 0.f;

#pragma unroll 8
    for (int d = 0; d < DIM; d++) {
        const float fi0 = Fi[ia * LD + d];
        const float fi1 = Fi[(ia + 1) * LD + d];
        const float fj0 = Fj[ja * LD + d];
        const float fj1 = Fj[(ja + 1) * LD + d];
        float x;
        x = fi0 - fj0; a00 = fmaf(x, x, a00);
        x = fi0 - fj1; a01 = fmaf(x, x, a01);
        x = fi1 - fj0; a10 = fmaf(x, x, a10);
        x = fi1 - fj1; a11 = fmaf(x, x, a11);
    }

    const int i = i0 + ia;
    const int j = j0 + ja;
    g_D[i * B + j]           = sqrtf(a00);
    g_D[i * B + j + 1]       = sqrtf(a01);
    g_D[(i + 1) * B + j]     = sqrtf(a10);
    g_D[(i + 1) * B + j + 1] = sqrtf(a11);
}

// ---------------------------------------------------------------------------
// Kernel 2: triplet reduction + fused finalize.
// One block per anchor row. Negatives packed into float4 chunks with +1e30
// sentinel padding (relu kills sentinel terms). Threads split into G groups
// that partition the positives; each thread holds one float4 of negatives in
// registers. G chosen at runtime from nn so sentinel waste stays minimal.
// Last block to finish computes the final scalar and resets accumulators.
// ---------------------------------------------------------------------------
__global__ __launch_bounds__(256) void triplet_kernel(const int* __restrict__ mask,
                                                      float* __restrict__ out) {
    __shared__ float  s_pos[B];      // d + margin
    __shared__ float4 s_neg4[B / 4]; // 512 slots, sentinel padded
    __shared__ int    s_cnt[2];
    __shared__ float  s_wsum[8];

    const int i   = blockIdx.x;
    const int tid = threadIdx.x;
    float* s_neg = (float*)s_neg4;

    if (tid < 2) s_cnt[tid] = 0;
    // sentinel-fill all 512 neg slots (128 float4 stores)
    if (tid < 128) s_neg4[tid] = make_float4(1e30f, 1e30f, 1e30f, 1e30f);
    __syncthreads();

    // Partition row i into positive / negative distance lists.
    for (int j = tid; j < B; j += 256) {
        const float d = g_D[i * B + j];
        const int   m = mask[i * B + j];
        if (m != 0) {
            const int p = atomicAdd(&s_cnt[0], 1);
            s_pos[p] = d + MARGIN;
        } else if (j != i) {
            const int p = atomicAdd(&s_cnt[1], 1);
            s_neg[p] = d;
        }
    }
    __syncthreads();

    const int np = s_cnt[0];
    const int nn = s_cnt[1];

    float local = 0.f;
    if (nn <= 256) {
        // 4 groups of 64 threads; each group covers all <=64 chunks,
        // partitions positives 4 ways.
        const int g   = tid & 63;
        const int grp = tid >> 6;
        const float4 n4 = s_neg4[g];
        for (int j = grp; j < np; j += 4) {
            const float pj = s_pos[j];
            local += fmaxf(pj - n4.x, 0.f);
            local += fmaxf(pj - n4.y, 0.f);
            local += fmaxf(pj - n4.z, 0.f);
            local += fmaxf(pj - n4.w, 0.f);
        }
    } else {
        // 2 groups of 128 threads; covers all <=128 chunks (nn <= 511).
        const int g   = tid & 127;
        const int grp = tid >> 7;
        const float4 n4 = s_neg4[g];
        for (int j = grp; j < np; j += 2) {
            const float pj = s_pos[j];
            local += fmaxf(pj - n4.x, 0.f);
            local += fmaxf(pj - n4.y, 0.f);
            local += fmaxf(pj - n4.z, 0.f);
            local += fmaxf(pj - n4.w, 0.f);
        }
    }

    // Block reduce
#pragma unroll
    for (int off = 16; off; off >>= 1)
        local += __shfl_down_sync(0xffffffffu, local, off);
    if ((tid & 31) == 0) s_wsum[tid >> 5] = local;
    __syncthreads();

    if (tid == 0) {
        float s = 0.f;
#pragma unroll
        for (int w = 0; w < 8; w++) s += s_wsum[w];
        atomicAdd(&g_num, (double)s);
        atomicAdd(&g_den, (unsigned long long)np * (unsigned long long)nn);
        __threadfence();
        const unsigned int ticket = atomicAdd(&g_done, 1u);
        if (ticket == gridDim.x - 1) {
            // All blocks' atomics are visible (they fenced before ticketing).
            const double num = atomicAdd(&g_num, 0.0);
            const unsigned long long den = atomicAdd(&g_den, 0ull);
            out[0] = (den > 0ull) ? (float)(num / (double)den) : 0.0f;
            // Reset state for the next graph replay.
            g_num  = 0.0;
            g_den  = 0ull;
            __threadfence();
            g_done = 0u;
        }
    }
}

// ---------------------------------------------------------------------------
extern "C" void kernel_launch(void* const* d_in, const int* in_sizes, int n_in,
                              void* d_out, int out_size) {
    const float* features = (const float*)d_in[0];   // [512,128] f32
    const int*   mask     = (const int*)d_in[1];     // [512,512] i32
    float* out = (float*)d_out;

    dim3 grid1(B / TS, B / TS);  // 16 x 16 = 256 blocks
    dist_kernel<<<grid1, 256>>>(features);
    triplet_kernel<<<B, 256>>>(mask, out);
}

// round 3
// speedup vs baseline: 1.1648x; 1.0659x over previous
#include <cuda_runtime.h>
#include <cuda_bf16.h>

#define B      512
#define DIM    128
#define MARGIN 0.2f
#define EPSF   1e-6f
#define BIGF   1e30f

// Scratch state (allocation-free rule). Statics init to zero; the triplet
// kernel's last block resets them after use, so every call leaves them zero.
__device__ float g_D[B * B];
__device__ double g_num = 0.0;
__device__ unsigned long long g_den = 0ull;
__device__ unsigned int g_done = 0u;

// ---------------------------------------------------------------------------
// Kernel 1: pairwise distances (unchanged from R2 — ~issue bound, adequate).
// ---------------------------------------------------------------------------
#define TS 32
#define LD 129
__global__ __launch_bounds__(256) void dist_kernel(const float* __restrict__ F) {
    __shared__ float Fi[TS * LD];   // holds fi + eps
    __shared__ float Fj[TS * LD];

    const int tx = threadIdx.x & 15;
    const int ty = threadIdx.x >> 4;
    const int i0 = blockIdx.y * TS;
    const int j0 = blockIdx.x * TS;

    for (int idx = threadIdx.x; idx < TS * DIM; idx += 256) {
        const int r = idx >> 7;
        const int d = idx & 127;
        Fi[r * LD + d] = F[(i0 + r) * DIM + d] + EPSF;
        Fj[r * LD + d] = F[(j0 + r) * DIM + d];
    }
    __syncthreads();

    const int ia = 2 * ty;
    const int ja = 2 * tx;
    float a00 = 0.f, a01 = 0.f, a10 = 0.f, a11 = 0.f;

#pragma unroll 8
    for (int d = 0; d < DIM; d++) {
        const float fi0 = Fi[ia * LD + d];
        const float fi1 = Fi[(ia + 1) * LD + d];
        const float fj0 = Fj[ja * LD + d];
        const float fj1 = Fj[(ja + 1) * LD + d];
        float x;
        x = fi0 - fj0; a00 = fmaf(x, x, a00);
        x = fi0 - fj1; a01 = fmaf(x, x, a01);
        x = fi1 - fj0; a10 = fmaf(x, x, a10);
        x = fi1 - fj1; a11 = fmaf(x, x, a11);
    }

    const int i = i0 + ia;
    const int j = j0 + ja;
    g_D[i * B + j]           = sqrtf(a00);
    g_D[i * B + j + 1]       = sqrtf(a01);
    g_D[(i + 1) * B + j]     = sqrtf(a10);
    g_D[(i + 1) * B + j + 1] = sqrtf(a11);
}

// ---------------------------------------------------------------------------
// Kernel 2: triplet reduction, sort-based (O(n log^2 n) instead of O(np*nn)).
// Per anchor row i:
//   1. ballot-compact D row into s_pos (d+margin) / s_neg (d), BIGF-padded.
//   2. bitonic-sort the 512 neg slots ascending.
//   3. prefix-sum the first nn sorted negs (shuffle scan), pre[c] = sum of c
//      smallest negatives.
//   4. per positive p: c = lower_bound(p);  contribution = c*p - pre[c].
// Exact: ties (n == p) contribute 0 regardless of boundary side.
// Last block finalizes the scalar and resets state.
// ---------------------------------------------------------------------------
__global__ __launch_bounds__(256) void triplet_kernel(const int* __restrict__ mask,
                                                      float* __restrict__ out) {
    __shared__ float s_pos[B];
    __shared__ float s_neg[B];
    __shared__ float s_pre[B + 1];  // pre[c] = sum of first c sorted negatives
    __shared__ float s_wt[8];
    __shared__ int   s_cnt[2];
    __shared__ float s_wsum[8];

    const int i    = blockIdx.x;
    const int tid  = threadIdx.x;
    const int lane = tid & 31;
    const int warp = tid >> 5;
    const unsigned FULL = 0xffffffffu;

    if (tid < 2) s_cnt[tid] = 0;
    // pad neg slots with BIGF (sorts to the end, never < any finite p)
    s_neg[tid]       = BIGF;
    s_neg[tid + 256] = BIGF;
    __syncthreads();

    // ---- 1. classify + ballot compaction (1 shared atomic per warp/class) --
#pragma unroll
    for (int r = 0; r < 2; r++) {
        const int j = tid + 256 * r;
        const float d = g_D[i * B + j];
        const int   m = mask[i * B + j];
        const bool isp = (m != 0);
        const bool isn = (!isp) && (j != i);
        const unsigned bp = __ballot_sync(FULL, isp);
        const unsigned bn = __ballot_sync(FULL, isn);
        int basep = 0, basen = 0;
        if (lane == 0) {
            basep = atomicAdd(&s_cnt[0], __popc(bp));
            basen = atomicAdd(&s_cnt[1], __popc(bn));
        }
        basep = __shfl_sync(FULL, basep, 0);
        basen = __shfl_sync(FULL, basen, 0);
        const unsigned lt = (1u << lane) - 1u;
        if (isp) s_pos[basep + __popc(bp & lt)] = d + MARGIN;
        if (isn) s_neg[basen + __popc(bn & lt)] = d;
    }
    __syncthreads();

    const int np = s_cnt[0];
    const int nn = s_cnt[1];

    // ---- 2. bitonic sort of 512 slots, ascending ---------------------------
#pragma unroll
    for (int k = 2; k <= B; k <<= 1) {
        for (int j = k >> 1; j > 0; j >>= 1) {
            const int idx = ((tid & ~(j - 1)) << 1) | (tid & (j - 1));
            const int prt = idx | j;
            const bool asc = ((idx & k) == 0);
            const float a = s_neg[idx];
            const float b = s_neg[prt];
            const float lo = fminf(a, b);
            const float hi = fmaxf(a, b);
            s_neg[idx] = asc ? lo : hi;
            s_neg[prt] = asc ? hi : lo;
            __syncthreads();
        }
    }

    // ---- 3. prefix sums of sorted negatives (2 elems/thread, shuffle scan) -
    {
        const int e0 = 2 * tid;
        const float v0 = (e0     < nn) ? s_neg[e0]     : 0.f;
        const float v1 = (e0 + 1 < nn) ? s_neg[e0 + 1] : 0.f;
        const float tsum = v0 + v1;
        float inc = tsum;
#pragma unroll
        for (int off = 1; off < 32; off <<= 1) {
            const float y = __shfl_up_sync(FULL, inc, off);
            if (lane >= off) inc += y;
        }
        if (lane == 31) s_wt[warp] = inc;
        __syncthreads();
        if (tid == 0) {
            float run = 0.f;
#pragma unroll
            for (int w = 0; w < 8; w++) { const float t = s_wt[w]; s_wt[w] = run; run += t; }
        }
        __syncthreads();
        const float excl = s_wt[warp] + (inc - tsum);  // sum of elems before e0
        s_pre[e0 + 1] = excl + v0;
        s_pre[e0 + 2] = excl + v0 + v1;
        if (tid == 0) s_pre[0] = 0.f;
    }
    __syncthreads();

    // ---- 4. per-positive binary search + closed-form sum -------------------
    float local = 0.f;
    for (int j = tid; j < np; j += 256) {
        const float p = s_pos[j];
        int c = 0;  // count of sorted negs < p
#pragma unroll
        for (int s = 256; s > 0; s >>= 1) {
            if (c + s <= B && s_neg[c + s - 1] < p) c += s;
        }
        local += (float)c * p - s_pre[c];
    }

    // ---- block reduce + fused finalize --------------------------------------
#pragma unroll
    for (int off = 16; off; off >>= 1)
        local += __shfl_down_sync(FULL, local, off);
    if (lane == 0) s_wsum[warp] = local;
    __syncthreads();

    if (tid == 0) {
        float s = 0.f;
#pragma unroll
        for (int w = 0; w < 8; w++) s += s_wsum[w];
        atomicAdd(&g_num, (double)s);
        atomicAdd(&g_den, (unsigned long long)np * (unsigned long long)nn);
        __threadfence();
        const unsigned int ticket = atomicAdd(&g_done, 1u);
        if (ticket == gridDim.x - 1) {
            const double num = atomicAdd(&g_num, 0.0);
            const unsigned long long den = atomicAdd(&g_den, 0ull);
            out[0] = (den > 0ull) ? (float)(num / (double)den) : 0.0f;
            g_num  = 0.0;
            g_den  = 0ull;
            __threadfence();
            g_done = 0u;
        }
    }
}

// ---------------------------------------------------------------------------
extern "C" void kernel_launch(void* const* d_in, const int* in_sizes, int n_in,
                              void* d_out, int out_size) {
    const float* features = (const float*)d_in[0];   // [512,128] f32
    const int*   mask     = (const int*)d_in[1];     // [512,512] i32
    float* out = (float*)d_out;

    dim3 grid1(B / TS, B / TS);  // 16 x 16 = 256 blocks
    dist_kernel<<<grid1, 256>>>(features);
    triplet_kernel<<<B, 256>>>(mask, out);
}

// round 4
// speedup vs baseline: 1.4324x; 1.2297x over previous
#include <cuda_runtime.h>
#include <cuda_bf16.h>

#define B      512
#define DIM    128
#define MARGIN 0.2f
#define EPSF   1e-6f
#define BIGF   1e30f
#define FULLM  0xffffffffu

// Scratch state (allocation-free rule). Statics init to zero; the triplet
// kernel's last block resets them after use, so every call leaves them zero.
__device__ float g_D[B * B];
__device__ double g_num = 0.0;
__device__ unsigned long long g_den = 0ull;
__device__ unsigned int g_done = 0u;

// ---------------------------------------------------------------------------
// Kernel 1: pairwise distances via norm expansion (pure-FMA inner loop).
//   u_i = f_i + eps;  D[i,j]^2 = |u_i|^2 + |f_j|^2 - 2 u_i . f_j
// Tile: 32 (i) x 64 (j), 128 blocks = one wave. 256 threads, 2x4 micro-tile.
// Dynamic smem (~50KB): Fi[32][130] (holds u), Fj[64][130], norms.
// ---------------------------------------------------------------------------
#define LD2 130
__global__ __launch_bounds__(256) void dist_kernel(const float* __restrict__ F) {
    extern __shared__ float sm[];
    float* Fi   = sm;                  // 32*130
    float* Fj   = Fi + 32 * LD2;       // 64*130
    float* s_ni = Fj + 64 * LD2;       // 32
    float* s_nj = s_ni + 32;           // 64

    const int tid = threadIdx.x;
    const int tx  = tid & 15;          // j dim: cols tx + 16c, c=0..3
    const int ty  = tid >> 4;          // i dim: rows ty + 16r, r=0..1
    const int i0  = blockIdx.y * 32;
    const int j0  = blockIdx.x * 64;

    // Load tiles (coalesced global, conflict-free STS)
    for (int idx = tid; idx < 96 * DIM; idx += 256) {
        const int r = idx >> 7;
        const int d = idx & 127;
        if (r < 32) Fi[r * LD2 + d] = F[(i0 + r) * DIM + d] + EPSF;
        else        Fj[(r - 32) * LD2 + d] = F[(j0 + r - 32) * DIM + d];
    }
    __syncthreads();

    // Row norms: warp w handles rows w + 8t (96 rows total)
    {
        const int lane = tid & 31;
        const int w    = tid >> 5;
#pragma unroll
        for (int t = 0; t < 12; t++) {
            const int r = w + 8 * t;
            const float* base = (r < 32) ? (Fi + r * LD2) : (Fj + (r - 32) * LD2);
            float s = 0.f;
#pragma unroll
            for (int q = 0; q < 4; q++) {
                const float x = base[lane + 32 * q];
                s = fmaf(x, x, s);
            }
#pragma unroll
            for (int off = 16; off; off >>= 1) s += __shfl_down_sync(FULLM, s, off);
            if (lane == 0) { if (r < 32) s_ni[r] = s; else s_nj[r - 32] = s; }
        }
    }
    __syncthreads();

    float acc[2][4] = {};
#pragma unroll 4
    for (int d = 0; d < DIM; d += 2) {
        const float2 a0 = *(const float2*)&Fi[(ty     ) * LD2 + d];
        const float2 a1 = *(const float2*)&Fi[(ty + 16) * LD2 + d];
        const float2 b0 = *(const float2*)&Fj[(tx     ) * LD2 + d];
        const float2 b1 = *(const float2*)&Fj[(tx + 16) * LD2 + d];
        const float2 b2 = *(const float2*)&Fj[(tx + 32) * LD2 + d];
        const float2 b3 = *(const float2*)&Fj[(tx + 48) * LD2 + d];
        acc[0][0] = fmaf(a0.x, b0.x, fmaf(a0.y, b0.y, acc[0][0]));
        acc[0][1] = fmaf(a0.x, b1.x, fmaf(a0.y, b1.y, acc[0][1]));
        acc[0][2] = fmaf(a0.x, b2.x, fmaf(a0.y, b2.y, acc[0][2]));
        acc[0][3] = fmaf(a0.x, b3.x, fmaf(a0.y, b3.y, acc[0][3]));
        acc[1][0] = fmaf(a1.x, b0.x, fmaf(a1.y, b0.y, acc[1][0]));
        acc[1][1] = fmaf(a1.x, b1.x, fmaf(a1.y, b1.y, acc[1][1]));
        acc[1][2] = fmaf(a1.x, b2.x, fmaf(a1.y, b2.y, acc[1][2]));
        acc[1][3] = fmaf(a1.x, b3.x, fmaf(a1.y, b3.y, acc[1][3]));
    }

#pragma unroll
    for (int r = 0; r < 2; r++) {
        const float ni = s_ni[ty + 16 * r];
        const int   i  = i0 + ty + 16 * r;
#pragma unroll
        for (int c = 0; c < 4; c++) {
            const float d2 = ni + s_nj[tx + 16 * c] - 2.f * acc[r][c];
            g_D[i * B + j0 + tx + 16 * c] = sqrtf(fmaxf(d2, 0.f));
        }
    }
}

// ---------------------------------------------------------------------------
// Kernel 2: triplet reduction, hybrid register/shfl bitonic sort.
// Thread holds elements e=tid and e=tid+256. Stages:
//   j<=16  -> shfl_xor (no barrier)   [35 stages]
//   j=256  -> intra-thread            [1 stage]
//   j=32/64/128 -> smem exchange, double-buffered (s_neg/s_pre), 1 bar each [9]
// Then prefix-sum + per-positive binary search (closed-form relu sum).
// ---------------------------------------------------------------------------
#define SHFL_STAGE(k, j) {                                                    \
    const float p0 = __shfl_xor_sync(FULLM, v0, (j));                         \
    const float p1 = __shfl_xor_sync(FULLM, v1, (j));                         \
    const bool lower = ((lane & (j)) == 0);                                   \
    const bool a0 = ((tid & (k)) == 0);                                       \
    const bool a1 = (((tid + 256) & (k)) == 0);                               \
    v0 = (lower == a0) ? fminf(v0, p0) : fmaxf(v0, p0);                       \
    v1 = (lower == a1) ? fminf(v1, p1) : fmaxf(v1, p1); }

#define SMEM_STAGE(k, j) {                                                    \
    float* ba = phase ? s_pre : s_neg;                                        \
    ba[tid] = v0; ba[tid + 256] = v1;                                         \
    __syncthreads();                                                          \
    const float p0 = ba[tid ^ (j)];                                           \
    const float p1 = ba[(tid ^ (j)) + 256];                                   \
    const bool lower = ((tid & (j)) == 0);                                    \
    const bool a0 = ((tid & (k)) == 0);                                       \
    const bool a1 = (((tid + 256) & (k)) == 0);                               \
    v0 = (lower == a0) ? fminf(v0, p0) : fmaxf(v0, p0);                       \
    v1 = (lower == a1) ? fminf(v1, p1) : fmaxf(v1, p1);                       \
    phase ^= 1; }

__global__ __launch_bounds__(256) void triplet_kernel(const int* __restrict__ mask,
                                                      float* __restrict__ out) {
    __shared__ float s_pos[B];
    __shared__ float s_neg[B];
    __shared__ float s_pre[B + 1];   // doubles as sort exchange buffer
    __shared__ float s_wt[8];
    __shared__ int   s_cnt[2];
    __shared__ float s_wsum[8];

    const int i    = blockIdx.x;
    const int tid  = threadIdx.x;
    const int lane = tid & 31;
    const int warp = tid >> 5;

    if (tid < 2) s_cnt[tid] = 0;
    s_neg[tid]       = BIGF;
    s_neg[tid + 256] = BIGF;
    __syncthreads();

    // ---- classify + ballot compaction ----
#pragma unroll
    for (int r = 0; r < 2; r++) {
        const int j = tid + 256 * r;
        const float d = g_D[i * B + j];
        const int   m = mask[i * B + j];
        const bool isp = (m != 0);
        const bool isn = (!isp) && (j != i);
        const unsigned bp = __ballot_sync(FULLM, isp);
        const unsigned bn = __ballot_sync(FULLM, isn);
        int basep = 0, basen = 0;
        if (lane == 0) {
            basep = atomicAdd(&s_cnt[0], __popc(bp));
            basen = atomicAdd(&s_cnt[1], __popc(bn));
        }
        basep = __shfl_sync(FULLM, basep, 0);
        basen = __shfl_sync(FULLM, basen, 0);
        const unsigned lt = (1u << lane) - 1u;
        if (isp) s_pos[basep + __popc(bp & lt)] = d + MARGIN;
        if (isn) s_neg[basen + __popc(bn & lt)] = d;
    }
    __syncthreads();

    const int np = s_cnt[0];
    const int nn = s_cnt[1];

    // ---- hybrid bitonic sort of 512 (BIGF-padded), ascending ----
    float v0 = s_neg[tid];
    float v1 = s_neg[tid + 256];
    int phase = 0;

    SHFL_STAGE(2, 1)
    SHFL_STAGE(4, 2)   SHFL_STAGE(4, 1)
    SHFL_STAGE(8, 4)   SHFL_STAGE(8, 2)   SHFL_STAGE(8, 1)
    SHFL_STAGE(16, 8)  SHFL_STAGE(16, 4)  SHFL_STAGE(16, 2)  SHFL_STAGE(16, 1)
    SHFL_STAGE(32, 16) SHFL_STAGE(32, 8)  SHFL_STAGE(32, 4)  SHFL_STAGE(32, 2)  SHFL_STAGE(32, 1)
    SMEM_STAGE(64, 32)
    SHFL_STAGE(64, 16) SHFL_STAGE(64, 8)  SHFL_STAGE(64, 4)  SHFL_STAGE(64, 2)  SHFL_STAGE(64, 1)
    SMEM_STAGE(128, 64) SMEM_STAGE(128, 32)
    SHFL_STAGE(128, 16) SHFL_STAGE(128, 8) SHFL_STAGE(128, 4) SHFL_STAGE(128, 2) SHFL_STAGE(128, 1)
    SMEM_STAGE(256, 128) SMEM_STAGE(256, 64) SMEM_STAGE(256, 32)
    SHFL_STAGE(256, 16) SHFL_STAGE(256, 8) SHFL_STAGE(256, 4) SHFL_STAGE(256, 2) SHFL_STAGE(256, 1)
    { const float lo = fminf(v0, v1), hi = fmaxf(v0, v1); v0 = lo; v1 = hi; }   // k=512, j=256
    SMEM_STAGE(512, 128) SMEM_STAGE(512, 64) SMEM_STAGE(512, 32)
    SHFL_STAGE(512, 16) SHFL_STAGE(512, 8) SHFL_STAGE(512, 4) SHFL_STAGE(512, 2) SHFL_STAGE(512, 1)

    __syncthreads();            // last exchange buffer may still be being read
    s_neg[tid]       = v0;      // sorted array, ascending; BIGF pads at end
    s_neg[tid + 256] = v1;
    __syncthreads();

    // ---- prefix sums of sorted negatives (2 elems/thread, shuffle scan) ----
    {
        const int e0 = 2 * tid;
        const float x0 = (e0     < nn) ? s_neg[e0]     : 0.f;
        const float x1 = (e0 + 1 < nn) ? s_neg[e0 + 1] : 0.f;
        const float tsum = x0 + x1;
        float inc = tsum;
#pragma unroll
        for (int off = 1; off < 32; off <<= 1) {
            const float y = __shfl_up_sync(FULLM, inc, off);
            if (lane >= off) inc += y;
        }
        if (lane == 31) s_wt[warp] = inc;
        __syncthreads();
        if (tid == 0) {
            float run = 0.f;
#pragma unroll
            for (int w = 0; w < 8; w++) { const float t = s_wt[w]; s_wt[w] = run; run += t; }
        }
        __syncthreads();
        const float excl = s_wt[warp] + (inc - tsum);
        s_pre[e0 + 1] = excl + x0;
        s_pre[e0 + 2] = excl + x0 + x1;
        if (tid == 0) s_pre[0] = 0.f;
    }
    __syncthreads();

    // ---- per-positive binary search + closed-form sum ----
    float local = 0.f;
    for (int j = tid; j < np; j += 256) {
        const float p = s_pos[j];
        int c = 0;
#pragma unroll
        for (int s = 256; s > 0; s >>= 1) {
            if (c + s <= B && s_neg[c + s - 1] < p) c += s;
        }
        local += (float)c * p - s_pre[c];
    }

    // ---- block reduce + fused finalize ----
#pragma unroll
    for (int off = 16; off; off >>= 1)
        local += __shfl_down_sync(FULLM, local, off);
    if (lane == 0) s_wsum[warp] = local;
    __syncthreads();

    if (tid == 0) {
        float s = 0.f;
#pragma unroll
        for (int w = 0; w < 8; w++) s += s_wsum[w];
        atomicAdd(&g_num, (double)s);
        atomicAdd(&g_den, (unsigned long long)np * (unsigned long long)nn);
        __threadfence();
        const unsigned int ticket = atomicAdd(&g_done, 1u);
        if (ticket == gridDim.x - 1) {
            const double num = atomicAdd(&g_num, 0.0);
            const unsigned long long den = atomicAdd(&g_den, 0ull);
            out[0] = (den > 0ull) ? (float)(num / (double)den) : 0.0f;
            g_num  = 0.0;
            g_den  = 0ull;
            __threadfence();
            g_done = 0u;
        }
    }
}

// ---------------------------------------------------------------------------
extern "C" void kernel_launch(void* const* d_in, const int* in_sizes, int n_in,
                              void* d_out, int out_size) {
    const float* features = (const float*)d_in[0];   // [512,128] f32
    const int*   mask     = (const int*)d_in[1];     // [512,512] i32
    float* out = (float*)d_out;

    const int smem_bytes = (32 * LD2 + 64 * LD2 + 96) * (int)sizeof(float);
    static bool attr_set = false;
    if (!attr_set) {
        cudaFuncSetAttribute(dist_kernel, cudaFuncAttributeMaxDynamicSharedMemorySize,
                             smem_bytes);
        attr_set = true;
    }

    dim3 grid1(B / 64, B / 32);   // 8 x 16 = 128 blocks, single wave
    dist_kernel<<<grid1, 256, smem_bytes>>>(features);
    triplet_kernel<<<B, 256>>>(mask, out);
}